// round 16
// baseline (speedup 1.0000x reference)
#include <cuda_runtime.h>

#define BB 4
#define NN 4096
#define HH 16
#define DD 64
#define HD (HH*DD)          // 1024
#define BH (BB*HH)          // 64
#define CH 16
#define CHTOK (NN/CH)       // 256
#define EPSZ 1e-6f
#define NTILE (BB*NN/64)    // 256 token tiles

#define KVSTR 72            // ==8 mod 32: conflict-free frags
#define QSTR  68            // ==4 mod 32
#define CSTR  72

// out_kernel dynamic smem: Qp[2][64][QSTR] + C[2 groups][2 stages][64][CSTR] + Ksm[2][64]
#define OUT_QP_F   (2*64*QSTR)
#define OUT_CS_F   (4*64*CSTR)
#define OUT_KS_F   (2*64)
#define SMEM_OUT   ((OUT_QP_F + OUT_CS_F + OUT_KS_F) * (int)sizeof(float))  // 109,056 B

__device__ float g_KVpart[CH*BH*DD*DD];   // 16 MB
__device__ float g_KSpart[CH*BH*DD];
__device__ float g_C[BH*DD*DD];           // tf32-rna-pre-rounded
__device__ float g_Ksum[BH*DD];

__device__ __forceinline__ float phi(float x) { return x > 0.0f ? x + 1.0f : __expf(x); }

__device__ __forceinline__ float tf32r(float x) {
    unsigned u;
    asm("cvt.rna.tf32.f32 %0, %1;" : "=r"(u) : "f"(x));
    return __uint_as_float(u);
}
__device__ __forceinline__ float4 phi4(float4 v) {
    float4 r; r.x = phi(v.x); r.y = phi(v.y); r.z = phi(v.z); r.w = phi(v.w);
    return r;
}
__device__ __forceinline__ float4 r4(float4 v) {
    float4 r; r.x = tf32r(v.x); r.y = tf32r(v.y); r.z = tf32r(v.z); r.w = tf32r(v.w);
    return r;
}

__device__ __forceinline__ void mma_tf32(float c[4],
    unsigned a0, unsigned a1, unsigned a2, unsigned a3,
    unsigned b0, unsigned b1)
{
    asm volatile(
        "mma.sync.aligned.m16n8k8.row.col.f32.tf32.tf32.f32 "
        "{%0,%1,%2,%3},{%4,%5,%6,%7},{%8,%9},{%0,%1,%2,%3};"
        : "+f"(c[0]), "+f"(c[1]), "+f"(c[2]), "+f"(c[3])
        : "r"(a0), "r"(a1), "r"(a2), "r"(a3), "r"(b0), "r"(b1));
}
__device__ __forceinline__ unsigned fb(float x) { return __float_as_uint(x); }

__device__ __forceinline__ void cpa16(void* smem, const void* g) {
    unsigned s = (unsigned)__cvta_generic_to_shared(smem);
    asm volatile("cp.async.ca.shared.global [%0], [%1], 16;" :: "r"(s), "l"(g));
}
#define CP_COMMIT() asm volatile("cp.async.commit_group;")
#define CP_WAIT(n)  asm volatile("cp.async.wait_group %0;" :: "n"(n))
#define BAR_GRP(id) asm volatile("bar.sync %0, 128;" :: "r"(id) : "memory")

// ---------------------------------------------------------------------------
// Phase 1: partial KV[d][m] = sum_t phi(K[t][d]) * V[t][m], tf32 MMA.
// 128 threads / 4 warps (32x32 quadrants). kpart aliased onto dead Ks stage
// after the mainloop -> smem 36.9KB -> 6 blocks/SM; launch_bounds(128,6).
// 1024 blocks x 128 threads.
// ---------------------------------------------------------------------------
__global__ __launch_bounds__(128, 6) void kv_partial_kernel(
    const float* __restrict__ key, const float* __restrict__ value)
{
    __shared__ float smbuf[4 * 32 * KVSTR];     // Ks[2][32][KVSTR] ++ Vs[2][32][KVSTR]
    float (*Ks)[32][KVSTR] = (float (*)[32][KVSTR])smbuf;
    float (*Vs)[32][KVSTR] = (float (*)[32][KVSTR])(smbuf + 2 * 32 * KVSTR);
    float (*kpart)[64]     = (float (*)[64])smbuf;   // reused after mainloop

    const int bx  = blockIdx.x;
    const int c   = bx % CH;
    const int bh  = bx / CH;
    const int b   = bh / HH;
    const int h   = bh % HH;
    const int tid = threadIdx.x;
    const int lane = tid & 31, warp = tid >> 5;  // 0..3
    const int dRow = (warp & 1) * 32;
    const int mCol = (warp >> 1) * 32;
    const int ar = lane >> 2;
    const int ac = lane & 3;

    const int ti  = tid >> 4;        // 0..7 (rows ti, ti+8, ti+16, ti+24)
    const int d4  = (tid & 15) * 4;

    const int n0 = c * CHTOK;
    const size_t gbase = (size_t)(b * NN + n0) * HD + h * DD + d4;
    const float* kp = key   + gbase + (size_t)ti * HD;
    const float* vp = value + gbase + (size_t)ti * HD;

    float acc[2][4][4];
#pragma unroll
    for (int mi = 0; mi < 2; mi++)
#pragma unroll
        for (int ni = 0; ni < 4; ni++)
#pragma unroll
            for (int j = 0; j < 4; j++) acc[mi][ni][j] = 0.0f;

    float4 ks4 = make_float4(0.f, 0.f, 0.f, 0.f);

#pragma unroll
    for (int i = 0; i < 4; i++) {
        cpa16(&Ks[0][ti + i * 8][d4], kp + (size_t)i * 8 * HD);
        cpa16(&Vs[0][ti + i * 8][d4], vp + (size_t)i * 8 * HD);
    }
    CP_COMMIT();

    const int NT = CHTOK / 32;       // 8
    for (int tile = 0; tile < NT; tile++) {
        const int cur = tile & 1;
        if (tile + 1 < NT) {
            const size_t off = (size_t)(tile + 1) * 32 * HD;
            const int nxt = cur ^ 1;
#pragma unroll
            for (int i = 0; i < 4; i++) {
                cpa16(&Ks[nxt][ti + i * 8][d4], kp + off + (size_t)i * 8 * HD);
                cpa16(&Vs[nxt][ti + i * 8][d4], vp + off + (size_t)i * 8 * HD);
            }
            CP_COMMIT();
            CP_WAIT(1);
        } else {
            CP_WAIT(0);
        }

#pragma unroll
        for (int i = 0; i < 4; i++) {
            const int t = ti + i * 8;
            const float4 p = phi4(*(const float4*)&Ks[cur][t][d4]);
            *(float4*)&Ks[cur][t][d4] = r4(p);
            ks4.x += p.x; ks4.y += p.y; ks4.z += p.z; ks4.w += p.w;
            *(float4*)&Vs[cur][t][d4] = r4(*(const float4*)&Vs[cur][t][d4]);
        }
        __syncthreads();

#pragma unroll
        for (int kk = 0; kk < 4; kk++) {
            const int k0 = kk * 8;
            unsigned a[2][4];
#pragma unroll
            for (int mi = 0; mi < 2; mi++) {
                const int base = dRow + 16 * mi;
                a[mi][0] = fb(Ks[cur][k0 + ac    ][base + ar    ]);
                a[mi][1] = fb(Ks[cur][k0 + ac    ][base + ar + 8]);
                a[mi][2] = fb(Ks[cur][k0 + ac + 4][base + ar    ]);
                a[mi][3] = fb(Ks[cur][k0 + ac + 4][base + ar + 8]);
            }
#pragma unroll
            for (int ni = 0; ni < 4; ni++) {
                const int nc = mCol + ni * 8 + ar;
                const unsigned b0 = fb(Vs[cur][k0 + ac    ][nc]);
                const unsigned b1 = fb(Vs[cur][k0 + ac + 4][nc]);
#pragma unroll
                for (int mi = 0; mi < 2; mi++)
                    mma_tf32(acc[mi][ni], a[mi][0], a[mi][1], a[mi][2], a[mi][3], b0, b1);
            }
        }
        __syncthreads();
    }

    // Ksum reduce in the now-dead Ks stage-0 region
    *(float4*)&kpart[ti][d4] = ks4;
    __syncthreads();
    if (tid < 64) {
        float s = 0.0f;
#pragma unroll
        for (int r = 0; r < 8; r++) s += kpart[r][tid];
        g_KSpart[(c * BH + bh) * DD + tid] = s;
    }

    float* outp = g_KVpart + (size_t)(c * BH + bh) * DD * DD;
#pragma unroll
    for (int mi = 0; mi < 2; mi++)
#pragma unroll
        for (int ni = 0; ni < 4; ni++) {
            const int col = mCol + ni * 8 + 2 * ac;
            const int r0  = dRow + 16 * mi + ar;
            *(float2*)(outp + r0 * DD + col)       = make_float2(acc[mi][ni][0], acc[mi][ni][1]);
            *(float2*)(outp + (r0 + 8) * DD + col) = make_float2(acc[mi][ni][2], acc[mi][ni][3]);
        }
}

// ---------------------------------------------------------------------------
// Phase 1.5: fold, split by d-quarter; stores C tf32-rna-rounded.
// (identical to R12)
// ---------------------------------------------------------------------------
__global__ __launch_bounds__(256) void fold_kernel(const float* __restrict__ W_out)
{
    __shared__ float KVq[16][64];
    __shared__ float Ws[64][68];

    const int bh  = blockIdx.x >> 2;
    const int dq  = blockIdx.x & 3;
    const int h   = bh % HH;
    const int d0  = dq * 16;
    const int tid = threadIdx.x;

    {
        const int lin = tid * 4;
        const int d = lin >> 6, m = lin & 63;
        float4 s = make_float4(0.f, 0.f, 0.f, 0.f);
#pragma unroll
        for (int cc = 0; cc < CH; cc++) {
            const float4 p = *(const float4*)(g_KVpart +
                (size_t)(cc * BH + bh) * DD * DD + (d0 + d) * DD + m);
            s.x += p.x; s.y += p.y; s.z += p.z; s.w += p.w;
        }
        *(float4*)&KVq[d][m] = s;
    }
#pragma unroll
    for (int i = 0; i < 4; i++) {
        const int lin = (tid + i * 256) * 4;
        const int j = lin >> 6, m = lin & 63;
        *(float4*)&Ws[j][m] = *(const float4*)(W_out + (size_t)j * HD + h * DD + m);
    }
    if (dq == 0 && tid < 64) {
        float s = 0.0f;
#pragma unroll
        for (int cc = 0; cc < CH; cc++) s += g_KSpart[(cc * BH + bh) * DD + tid];
        g_Ksum[bh * DD + tid] = s;
    }
    __syncthreads();

    const int d  = tid >> 4;
    const int j4 = (tid & 15) * 4;
    float a0 = 0.f, a1 = 0.f, a2 = 0.f, a3 = 0.f;
#pragma unroll 8
    for (int m = 0; m < 64; m++) {
        const float a = KVq[d][m];
        a0 += a * Ws[j4    ][m];
        a1 += a * Ws[j4 + 1][m];
        a2 += a * Ws[j4 + 2][m];
        a3 += a * Ws[j4 + 3][m];
    }
    float* cp = g_C + (size_t)bh * DD * DD + (d0 + d) * DD + j4;
    *(float4*)cp = make_float4(tf32r(a0), tf32r(a1), tf32r(a2), tf32r(a3));
}

// ---------------------------------------------------------------------------
// Phase 2: out[t][j] = b[j] + sum_h Z[t,h]*(Qphi[t,h,:] @ C[b,h][:,j]).
// R12 design + per-group DOUBLE-BUFFERED C tiles: C for head hd+2 is issued
// at the top of iteration p and waited with wait(1) -> a full iteration of
// L2-latency cover (fixes the serial CP_WAIT(0) stall ncu exposed).
// Dynamic smem 109KB, 2 blocks/SM. 256 blocks x 256 threads.
// ---------------------------------------------------------------------------
__global__ __launch_bounds__(256, 2) void out_kernel(
    const float* __restrict__ query, const float* __restrict__ b_out,
    float* __restrict__ out)
{
    extern __shared__ float sm[];
    float* Qp  = sm;                          // [2][64][QSTR]
    float* Cb  = sm + OUT_QP_F;               // [2][2][64][CSTR]
    float* Ksm = sm + OUT_QP_F + OUT_CS_F;    // [2][64]

#define QP(hs, r, c)      Qp[((hs) * 64 + (r)) * QSTR + (c)]
#define CS(hs, st, r, c)  Cb[((((hs) * 2 + (st)) * 64) + (r)) * CSTR + (c)]
#define KS(hs, i)         Ksm[(hs) * 64 + (i)]

    const int blk = blockIdx.x;
    const int b   = blk >> 6;               // NN/64 = 64 tiles per batch
    const int t0g = blk * 64;
    const int tid = threadIdx.x;
    const int lane = tid & 31, warp = tid >> 5;
    const int hs   = warp >> 2;             // head slot 0/1
    const int wq   = warp & 3;
    const int mRow = (wq & 1) * 32;
    const int nCol = (wq >> 1) * 32;
    const int ar = lane >> 2;
    const int ac = lane & 3;
    const int barid = 1 + hs;

    const int l   = tid & 127;
    const int rb  = l >> 4;                 // 0..7 row base (stride 8)
    const int cd4 = (l & 15) * 4;

    const float* qbase = query + (size_t)(t0g + rb) * HD + cd4;
    const float* cbase = g_C + (size_t)(b * HH) * DD * DD + rb * DD + cd4;
    const float* kbase = g_Ksum + (b * HH) * DD;

    float acc[2][4][4];
#pragma unroll
    for (int mi = 0; mi < 2; mi++)
#pragma unroll
        for (int ni = 0; ni < 4; ni++)
#pragma unroll
            for (int j = 0; j < 4; j++) acc[mi][ni][j] = 0.0f;

    float4 qbuf[8];
#pragma unroll
    for (int i = 0; i < 8; i++)
        qbuf[i] = *(const float4*)(qbase + hs * DD + (size_t)i * 8 * HD);

    // prologue: C for head hs into stage 0
#pragma unroll
    for (int i = 0; i < 8; i++)
        cpa16(&CS(hs, 0, rb + i * 8, cd4), cbase + (size_t)hs * DD * DD + i * 8 * DD);
    CP_COMMIT();

    for (int p = 0; p < 8; p++) {
        const int hd = 2 * p + hs;
        const int st = p & 1;

        // issue C for head hd+2 into the other stage (full iteration of cover)
        if (p < 7) {
#pragma unroll
            for (int i = 0; i < 8; i++)
                cpa16(&CS(hs, st ^ 1, rb + i * 8, cd4),
                      cbase + (size_t)(hd + 2) * DD * DD + i * 8 * DD);
            CP_COMMIT();
        }

        // Ksum for this head -> smem, rna-rounded
        if (l < 16)
            *(float4*)&KS(hs, l * 4) = r4(*(const float4*)(kbase + hd * DD + l * 4));

        // store phase: phi + rna + store
#pragma unroll
        for (int i = 0; i < 8; i++)
            *(float4*)&QP(hs, rb + i * 8, cd4) = r4(phi4(qbuf[i]));

        // hoisted prefetch: qbuf dead now
        if (p < 7) {
#pragma unroll
            for (int i = 0; i < 8; i++)
                qbuf[i] = *(const float4*)(qbase + (hd + 2) * DD + (size_t)i * 8 * HD);
        }

        if (p < 7) { CP_WAIT(1); } else { CP_WAIT(0); }
        BAR_GRP(barid);

        float tacc[2][4][4];
        float dacc[2][4];
#pragma unroll
        for (int mi = 0; mi < 2; mi++) {
#pragma unroll
            for (int ni = 0; ni < 4; ni++)
#pragma unroll
                for (int j = 0; j < 4; j++) tacc[mi][ni][j] = 0.0f;
#pragma unroll
            for (int j = 0; j < 4; j++) dacc[mi][j] = 0.0f;
        }

#pragma unroll
        for (int kk = 0; kk < 8; kk++) {
            const int k0 = kk * 8;
            unsigned a[2][4];
#pragma unroll
            for (int mi = 0; mi < 2; mi++) {
                const int r = mRow + mi * 16 + ar;
                a[mi][0] = fb(QP(hs, r,     k0 + ac    ));
                a[mi][1] = fb(QP(hs, r + 8, k0 + ac    ));
                a[mi][2] = fb(QP(hs, r,     k0 + ac + 4));
                a[mi][3] = fb(QP(hs, r + 8, k0 + ac + 4));
            }
            const unsigned kb0 = fb(KS(hs, k0 + ac    ));
            const unsigned kb1 = fb(KS(hs, k0 + ac + 4));
#pragma unroll
            for (int mi = 0; mi < 2; mi++)
                mma_tf32(dacc[mi], a[mi][0], a[mi][1], a[mi][2], a[mi][3], kb0, kb1);
#pragma unroll
            for (int ni = 0; ni < 4; ni++) {
                const int nc = nCol + ni * 8 + ar;
                const unsigned b0 = fb(CS(hs, st, k0 + ac,     nc));
                const unsigned b1 = fb(CS(hs, st, k0 + ac + 4, nc));
#pragma unroll
                for (int mi = 0; mi < 2; mi++)
                    mma_tf32(tacc[mi][ni], a[mi][0], a[mi][1], a[mi][2], a[mi][3], b0, b1);
            }
        }

#pragma unroll
        for (int mi = 0; mi < 2; mi++) {
            const float z0 = 1.0f / (dacc[mi][0] + EPSZ);
            const float z1 = 1.0f / (dacc[mi][2] + EPSZ);
#pragma unroll
            for (int ni = 0; ni < 4; ni++) {
                acc[mi][ni][0] += z0 * tacc[mi][ni][0];
                acc[mi][ni][1] += z0 * tacc[mi][ni][1];
                acc[mi][ni][2] += z1 * tacc[mi][ni][2];
                acc[mi][ni][3] += z1 * tacc[mi][ni][3];
            }
        }
        BAR_GRP(barid);
    }

    // merge head-group partials via group0/stage0 C buffer
    __syncthreads();
    if (hs == 1) {
#pragma unroll
        for (int mi = 0; mi < 2; mi++)
#pragma unroll
            for (int ni = 0; ni < 4; ni++) {
                const int r = mRow + mi * 16 + ar;
                const int ccol = nCol + ni * 8 + 2 * ac;
                *(float2*)&CS(0, 0, r,     ccol) = make_float2(acc[mi][ni][0], acc[mi][ni][1]);
                *(float2*)&CS(0, 0, r + 8, ccol) = make_float2(acc[mi][ni][2], acc[mi][ni][3]);
            }
    }
    __syncthreads();
    if (hs == 0) {
#pragma unroll
        for (int mi = 0; mi < 2; mi++)
#pragma unroll
            for (int ni = 0; ni < 4; ni++) {
                const int r = mRow + mi * 16 + ar;
                const int ccol = nCol + ni * 8 + 2 * ac;
                const float bj0 = b_out[ccol], bj1 = b_out[ccol + 1];
                const float2 o0 = *(const float2*)&CS(0, 0, r,     ccol);
                const float2 o1 = *(const float2*)&CS(0, 0, r + 8, ccol);
                *(float2*)(out + (size_t)(t0g + r) * DD + ccol) =
                    make_float2(acc[mi][ni][0] + o0.x + bj0, acc[mi][ni][1] + o0.y + bj1);
                *(float2*)(out + (size_t)(t0g + r + 8) * DD + ccol) =
                    make_float2(acc[mi][ni][2] + o1.x + bj0, acc[mi][ni][3] + o1.y + bj1);
            }
    }
#undef QP
#undef CS
#undef KS
}

// ---------------------------------------------------------------------------
extern "C" void kernel_launch(void* const* d_in, const int* in_sizes, int n_in,
                              void* d_out, int out_size)
{
    const float* q  = (const float*)d_in[0];
    const float* k  = (const float*)d_in[1];
    const float* v  = (const float*)d_in[2];
    const float* W  = (const float*)d_in[3];
    const float* bo = (const float*)d_in[4];
    float* out = (float*)d_out;

    static int attr_set = 0;
    if (!attr_set) {
        cudaFuncSetAttribute(out_kernel,
                             cudaFuncAttributeMaxDynamicSharedMemorySize, SMEM_OUT);
        attr_set = 1;
    }

    kv_partial_kernel<<<BH * CH, 128>>>(k, v);
    fold_kernel<<<BH * 4, 256>>>(W);
    out_kernel<<<NTILE, 256, SMEM_OUT>>>(q, bo, out);
}

// round 17
// speedup vs baseline: 1.0316x; 1.0316x over previous
#include <cuda_runtime.h>

#define BB 4
#define NN 4096
#define HH 16
#define DD 64
#define HD (HH*DD)          // 1024
#define BH (BB*HH)          // 64
#define CH 16
#define CHTOK (NN/CH)       // 256
#define EPSZ 1e-6f
#define NTILE (BB*NN/64)    // 256 token tiles

#define KVSTR 72            // ==8 mod 32: conflict-free frags
#define QSTR  68            // ==4 mod 32
#define CSTR  72

#define KV_TILE_F (32*KVSTR)
#define KV_SMEM (6*KV_TILE_F*(int)sizeof(float))   // 55,296 B (3 stages K + 3 stages V)

__device__ float g_KVpart[CH*BH*DD*DD];   // 16 MB
__device__ float g_KSpart[CH*BH*DD];
__device__ float g_C[BH*DD*DD];           // tf32-rna-pre-rounded
__device__ float g_Ksum[BH*DD];

__device__ __forceinline__ float phi(float x) { return x > 0.0f ? x + 1.0f : __expf(x); }

__device__ __forceinline__ float tf32r(float x) {
    unsigned u;
    asm("cvt.rna.tf32.f32 %0, %1;" : "=r"(u) : "f"(x));
    return __uint_as_float(u);
}
__device__ __forceinline__ float4 phi4(float4 v) {
    float4 r; r.x = phi(v.x); r.y = phi(v.y); r.z = phi(v.z); r.w = phi(v.w);
    return r;
}
__device__ __forceinline__ float4 r4(float4 v) {
    float4 r; r.x = tf32r(v.x); r.y = tf32r(v.y); r.z = tf32r(v.z); r.w = tf32r(v.w);
    return r;
}

__device__ __forceinline__ void mma_tf32(float c[4],
    unsigned a0, unsigned a1, unsigned a2, unsigned a3,
    unsigned b0, unsigned b1)
{
    asm volatile(
        "mma.sync.aligned.m16n8k8.row.col.f32.tf32.tf32.f32 "
        "{%0,%1,%2,%3},{%4,%5,%6,%7},{%8,%9},{%0,%1,%2,%3};"
        : "+f"(c[0]), "+f"(c[1]), "+f"(c[2]), "+f"(c[3])
        : "r"(a0), "r"(a1), "r"(a2), "r"(a3), "r"(b0), "r"(b1));
}
__device__ __forceinline__ unsigned fb(float x) { return __float_as_uint(x); }

__device__ __forceinline__ void cpa16(void* smem, const void* g) {
    unsigned s = (unsigned)__cvta_generic_to_shared(smem);
    asm volatile("cp.async.ca.shared.global [%0], [%1], 16;" :: "r"(s), "l"(g));
}
#define CP_COMMIT() asm volatile("cp.async.commit_group;")
#define CP_WAIT(n)  asm volatile("cp.async.wait_group %0;" :: "n"(n))
#define BAR_GRP(id) asm volatile("bar.sync %0, 128;" :: "r"(id) : "memory")

// ---------------------------------------------------------------------------
// Phase 1: partial KV[d][m] = sum_t phi(K[t][d]) * V[t][m], tf32 MMA.
// 128 threads / 4 warps (32x32 quadrants, 2.0 LDS/MMA). 3-STAGE cp.async
// pipeline with the proven 2-barrier structure: commit tile+2 at top,
// wait(2) -> two tile-groups in flight during compute (raises achieved
// HBM BW; R15 measured kv ~92% bound by achieved BW). Regs free (96).
// 1024 blocks x 128 threads, 55.3KB dynamic smem (4 blocks/SM).
// ---------------------------------------------------------------------------
__global__ __launch_bounds__(128) void kv_partial_kernel(
    const float* __restrict__ key, const float* __restrict__ value)
{
    extern __shared__ float smbuf[];            // 3 stages K ++ 3 stages V
    float (*Ks)[32][KVSTR] = (float (*)[32][KVSTR])smbuf;
    float (*Vs)[32][KVSTR] = (float (*)[32][KVSTR])(smbuf + 3 * KV_TILE_F);
    float (*kpart)[64]     = (float (*)[64])smbuf;   // reused after mainloop

    const int bx  = blockIdx.x;
    const int c   = bx % CH;
    const int bh  = bx / CH;
    const int b   = bh / HH;
    const int h   = bh % HH;
    const int tid = threadIdx.x;
    const int lane = tid & 31, warp = tid >> 5;  // 0..3
    const int dRow = (warp & 1) * 32;
    const int mCol = (warp >> 1) * 32;
    const int ar = lane >> 2;
    const int ac = lane & 3;

    const int ti  = tid >> 4;        // 0..7 (rows ti, ti+8, ti+16, ti+24)
    const int d4  = (tid & 15) * 4;

    const int n0 = c * CHTOK;
    const size_t gbase = (size_t)(b * NN + n0) * HD + h * DD + d4;
    const float* kp = key   + gbase + (size_t)ti * HD;
    const float* vp = value + gbase + (size_t)ti * HD;

    float acc[2][4][4];
#pragma unroll
    for (int mi = 0; mi < 2; mi++)
#pragma unroll
        for (int ni = 0; ni < 4; ni++)
#pragma unroll
            for (int j = 0; j < 4; j++) acc[mi][ni][j] = 0.0f;

    float4 ks4 = make_float4(0.f, 0.f, 0.f, 0.f);

    // prologue: tiles 0 and 1 into stages 0 and 1 (one commit group each)
#pragma unroll
    for (int s = 0; s < 2; s++) {
        const size_t off = (size_t)s * 32 * HD;
#pragma unroll
        for (int i = 0; i < 4; i++) {
            cpa16(&Ks[s][ti + i * 8][d4], kp + off + (size_t)i * 8 * HD);
            cpa16(&Vs[s][ti + i * 8][d4], vp + off + (size_t)i * 8 * HD);
        }
        CP_COMMIT();
    }

    const int NT = CHTOK / 32;       // 8
    int cur = 0;
    for (int tile = 0; tile < NT; tile++) {
        // issue tile+2 into stage (tile+2)%3 == (tile-1)%3 (freed by the
        // trailing barrier of iteration tile-1), then wait for tile's group
        if (tile + 2 < NT) {
            int nst = cur + 2; if (nst >= 3) nst -= 3;
            const size_t off = (size_t)(tile + 2) * 32 * HD;
#pragma unroll
            for (int i = 0; i < 4; i++) {
                cpa16(&Ks[nst][ti + i * 8][d4], kp + off + (size_t)i * 8 * HD);
                cpa16(&Vs[nst][ti + i * 8][d4], vp + off + (size_t)i * 8 * HD);
            }
            CP_COMMIT();
            CP_WAIT(2);
        } else if (tile + 1 < NT) {
            CP_WAIT(1);
        } else {
            CP_WAIT(0);
        }

        // RMW convert own chunks; accumulate Ksum from registers
#pragma unroll
        for (int i = 0; i < 4; i++) {
            const int t = ti + i * 8;
            const float4 p = phi4(*(const float4*)&Ks[cur][t][d4]);
            *(float4*)&Ks[cur][t][d4] = r4(p);
            ks4.x += p.x; ks4.y += p.y; ks4.z += p.z; ks4.w += p.w;
            *(float4*)&Vs[cur][t][d4] = r4(*(const float4*)&Vs[cur][t][d4]);
        }
        __syncthreads();

#pragma unroll
        for (int kk = 0; kk < 4; kk++) {
            const int k0 = kk * 8;
            unsigned a[2][4];
#pragma unroll
            for (int mi = 0; mi < 2; mi++) {
                const int base = dRow + 16 * mi;
                a[mi][0] = fb(Ks[cur][k0 + ac    ][base + ar    ]);
                a[mi][1] = fb(Ks[cur][k0 + ac    ][base + ar + 8]);
                a[mi][2] = fb(Ks[cur][k0 + ac + 4][base + ar    ]);
                a[mi][3] = fb(Ks[cur][k0 + ac + 4][base + ar + 8]);
            }
#pragma unroll
            for (int ni = 0; ni < 4; ni++) {
                const int nc = mCol + ni * 8 + ar;
                const unsigned b0 = fb(Vs[cur][k0 + ac    ][nc]);
                const unsigned b1 = fb(Vs[cur][k0 + ac + 4][nc]);
#pragma unroll
                for (int mi = 0; mi < 2; mi++)
                    mma_tf32(acc[mi][ni], a[mi][0], a[mi][1], a[mi][2], a[mi][3], b0, b1);
            }
        }
        __syncthreads();   // frees stage cur for the issue at top of tile+1
        cur = (cur == 2) ? 0 : cur + 1;
    }

    // Ksum reduce in the now-dead stage-0 region
    *(float4*)&kpart[ti][d4] = ks4;
    __syncthreads();
    if (tid < 64) {
        float s = 0.0f;
#pragma unroll
        for (int r = 0; r < 8; r++) s += kpart[r][tid];
        g_KSpart[(c * BH + bh) * DD + tid] = s;
    }

    float* outp = g_KVpart + (size_t)(c * BH + bh) * DD * DD;
#pragma unroll
    for (int mi = 0; mi < 2; mi++)
#pragma unroll
        for (int ni = 0; ni < 4; ni++) {
            const int col = mCol + ni * 8 + 2 * ac;
            const int r0  = dRow + 16 * mi + ar;
            *(float2*)(outp + r0 * DD + col)       = make_float2(acc[mi][ni][0], acc[mi][ni][1]);
            *(float2*)(outp + (r0 + 8) * DD + col) = make_float2(acc[mi][ni][2], acc[mi][ni][3]);
        }
}

// ---------------------------------------------------------------------------
// Phase 1.5: fold, split by d-quarter; stores C tf32-rna-rounded.
// (identical to R12/R15)
// ---------------------------------------------------------------------------
__global__ __launch_bounds__(256) void fold_kernel(const float* __restrict__ W_out)
{
    __shared__ float KVq[16][64];
    __shared__ float Ws[64][68];

    const int bh  = blockIdx.x >> 2;
    const int dq  = blockIdx.x & 3;
    const int h   = bh % HH;
    const int d0  = dq * 16;
    const int tid = threadIdx.x;

    {
        const int lin = tid * 4;
        const int d = lin >> 6, m = lin & 63;
        float4 s = make_float4(0.f, 0.f, 0.f, 0.f);
#pragma unroll
        for (int cc = 0; cc < CH; cc++) {
            const float4 p = *(const float4*)(g_KVpart +
                (size_t)(cc * BH + bh) * DD * DD + (d0 + d) * DD + m);
            s.x += p.x; s.y += p.y; s.z += p.z; s.w += p.w;
        }
        *(float4*)&KVq[d][m] = s;
    }
#pragma unroll
    for (int i = 0; i < 4; i++) {
        const int lin = (tid + i * 256) * 4;
        const int j = lin >> 6, m = lin & 63;
        *(float4*)&Ws[j][m] = *(const float4*)(W_out + (size_t)j * HD + h * DD + m);
    }
    if (dq == 0 && tid < 64) {
        float s = 0.0f;
#pragma unroll
        for (int cc = 0; cc < CH; cc++) s += g_KSpart[(cc * BH + bh) * DD + tid];
        g_Ksum[bh * DD + tid] = s;
    }
    __syncthreads();

    const int d  = tid >> 4;
    const int j4 = (tid & 15) * 4;
    float a0 = 0.f, a1 = 0.f, a2 = 0.f, a3 = 0.f;
#pragma unroll 8
    for (int m = 0; m < 64; m++) {
        const float a = KVq[d][m];
        a0 += a * Ws[j4    ][m];
        a1 += a * Ws[j4 + 1][m];
        a2 += a * Ws[j4 + 2][m];
        a3 += a * Ws[j4 + 3][m];
    }
    float* cp = g_C + (size_t)bh * DD * DD + (d0 + d) * DD + j4;
    *(float4*)cp = make_float4(tf32r(a0), tf32r(a1), tf32r(a2), tf32r(a3));
}

// ---------------------------------------------------------------------------
// Phase 2: out[t][j] = b[j] + sum_h Z[t,h]*(Qphi[t,h,:] @ C[b,h][:,j]).
// (identical to R12/R15 — 64-token tiles, two head groups, dot-MMA Z)
// ---------------------------------------------------------------------------
__global__ __launch_bounds__(256, 2) void out_kernel(
    const float* __restrict__ query, const float* __restrict__ b_out,
    float* __restrict__ out)
{
    __shared__ float Qp[2][64][QSTR];
    __shared__ float Cs[2][64][CSTR];
    __shared__ float Ksm[2][64];

    const int blk = blockIdx.x;
    const int b   = blk >> 6;               // NN/64 = 64 tiles per batch
    const int t0g = blk * 64;
    const int tid = threadIdx.x;
    const int lane = tid & 31, warp = tid >> 5;
    const int hs   = warp >> 2;             // head slot 0/1
    const int wq   = warp & 3;
    const int mRow = (wq & 1) * 32;
    const int nCol = (wq >> 1) * 32;
    const int ar = lane >> 2;
    const int ac = lane & 3;
    const int barid = 1 + hs;

    const int l   = tid & 127;
    const int rb  = l >> 4;                 // 0..7 row base (stride 8)
    const int cd4 = (l & 15) * 4;

    const float* qbase = query + (size_t)(t0g + rb) * HD + cd4;
    const float* cbase = g_C + (size_t)(b * HH) * DD * DD + rb * DD + cd4;
    const float* kbase = g_Ksum + (b * HH) * DD;

    float acc[2][4][4];
#pragma unroll
    for (int mi = 0; mi < 2; mi++)
#pragma unroll
        for (int ni = 0; ni < 4; ni++)
#pragma unroll
            for (int j = 0; j < 4; j++) acc[mi][ni][j] = 0.0f;

    float4 qbuf[8];
#pragma unroll
    for (int i = 0; i < 8; i++)
        qbuf[i] = *(const float4*)(qbase + hs * DD + (size_t)i * 8 * HD);

    for (int p = 0; p < 8; p++) {
        const int hd = 2 * p + hs;

#pragma unroll
        for (int i = 0; i < 8; i++)
            cpa16(&Cs[hs][rb + i * 8][cd4],
                  cbase + (size_t)hd * DD * DD + i * 8 * DD);
        CP_COMMIT();

        if (l < 16)
            *(float4*)&Ksm[hs][l * 4] = r4(*(const float4*)(kbase + hd * DD + l * 4));

#pragma unroll
        for (int i = 0; i < 8; i++)
            *(float4*)&Qp[hs][rb + i * 8][cd4] = r4(phi4(qbuf[i]));

        if (p < 7) {
#pragma unroll
            for (int i = 0; i < 8; i++)
                qbuf[i] = *(const float4*)(qbase + (hd + 2) * DD + (size_t)i * 8 * HD);
        }

        CP_WAIT(0);
        BAR_GRP(barid);

        float tacc[2][4][4];
        float dacc[2][4];
#pragma unroll
        for (int mi = 0; mi < 2; mi++) {
#pragma unroll
            for (int ni = 0; ni < 4; ni++)
#pragma unroll
                for (int j = 0; j < 4; j++) tacc[mi][ni][j] = 0.0f;
#pragma unroll
            for (int j = 0; j < 4; j++) dacc[mi][j] = 0.0f;
        }

#pragma unroll
        for (int kk = 0; kk < 8; kk++) {
            const int k0 = kk * 8;
            unsigned a[2][4];
#pragma unroll
            for (int mi = 0; mi < 2; mi++) {
                const int r = mRow + mi * 16 + ar;
                a[mi][0] = fb(Qp[hs][r    ][k0 + ac    ]);
                a[mi][1] = fb(Qp[hs][r + 8][k0 + ac    ]);
                a[mi][2] = fb(Qp[hs][r    ][k0 + ac + 4]);
                a[mi][3] = fb(Qp[hs][r + 8][k0 + ac + 4]);
            }
            const unsigned kb0 = fb(Ksm[hs][k0 + ac    ]);
            const unsigned kb1 = fb(Ksm[hs][k0 + ac + 4]);
#pragma unroll
            for (int mi = 0; mi < 2; mi++)
                mma_tf32(dacc[mi], a[mi][0], a[mi][1], a[mi][2], a[mi][3], kb0, kb1);
#pragma unroll
            for (int ni = 0; ni < 4; ni++) {
                const int nc = nCol + ni * 8 + ar;
                const unsigned b0 = fb(Cs[hs][k0 + ac    ][nc]);
                const unsigned b1 = fb(Cs[hs][k0 + ac + 4][nc]);
#pragma unroll
                for (int mi = 0; mi < 2; mi++)
                    mma_tf32(tacc[mi][ni], a[mi][0], a[mi][1], a[mi][2], a[mi][3], b0, b1);
            }
        }

#pragma unroll
        for (int mi = 0; mi < 2; mi++) {
            const float z0 = 1.0f / (dacc[mi][0] + EPSZ);
            const float z1 = 1.0f / (dacc[mi][2] + EPSZ);
#pragma unroll
            for (int ni = 0; ni < 4; ni++) {
                acc[mi][ni][0] += z0 * tacc[mi][ni][0];
                acc[mi][ni][1] += z0 * tacc[mi][ni][1];
                acc[mi][ni][2] += z1 * tacc[mi][ni][2];
                acc[mi][ni][3] += z1 * tacc[mi][ni][3];
            }
        }
        BAR_GRP(barid);
    }

    __syncthreads();
    if (hs == 1) {
#pragma unroll
        for (int mi = 0; mi < 2; mi++)
#pragma unroll
            for (int ni = 0; ni < 4; ni++) {
                const int r = mRow + mi * 16 + ar;
                const int ccol = nCol + ni * 8 + 2 * ac;
                *(float2*)&Cs[0][r    ][ccol] = make_float2(acc[mi][ni][0], acc[mi][ni][1]);
                *(float2*)&Cs[0][r + 8][ccol] = make_float2(acc[mi][ni][2], acc[mi][ni][3]);
            }
    }
    __syncthreads();
    if (hs == 0) {
#pragma unroll
        for (int mi = 0; mi < 2; mi++)
#pragma unroll
            for (int ni = 0; ni < 4; ni++) {
                const int r = mRow + mi * 16 + ar;
                const int ccol = nCol + ni * 8 + 2 * ac;
                const float bj0 = b_out[ccol], bj1 = b_out[ccol + 1];
                const float2 o0 = *(const float2*)&Cs[0][r    ][ccol];
                const float2 o1 = *(const float2*)&Cs[0][r + 8][ccol];
                *(float2*)(out + (size_t)(t0g + r) * DD + ccol) =
                    make_float2(acc[mi][ni][0] + o0.x + bj0, acc[mi][ni][1] + o0.y + bj1);
                *(float2*)(out + (size_t)(t0g + r + 8) * DD + ccol) =
                    make_float2(acc[mi][ni][2] + o1.x + bj0, acc[mi][ni][3] + o1.y + bj1);
            }
    }
}

// ---------------------------------------------------------------------------
extern "C" void kernel_launch(void* const* d_in, const int* in_sizes, int n_in,
                              void* d_out, int out_size)
{
    const float* q  = (const float*)d_in[0];
    const float* k  = (const float*)d_in[1];
    const float* v  = (const float*)d_in[2];
    const float* W  = (const float*)d_in[3];
    const float* bo = (const float*)d_in[4];
    float* out = (float*)d_out;

    static int attr_set = 0;
    if (!attr_set) {
        cudaFuncSetAttribute(kv_partial_kernel,
                             cudaFuncAttributeMaxDynamicSharedMemorySize, KV_SMEM);
        attr_set = 1;
    }

    kv_partial_kernel<<<BH * CH, 128, KV_SMEM>>>(k, v);
    fold_kernel<<<BH * 4, 256>>>(W);
    out_kernel<<<NTILE, 256>>>(q, bo, out);
}